// round 10
// baseline (speedup 1.0000x reference)
#include <cuda_runtime.h>
#include <cstdint>

// Problem constants
#define BB   4
#define SS   2048
#define DD   768
#define NH   4
#define KK   4
#define DH   192          // DD / NH
#define MM   (BB*SS)      // 8192 GEMM rows

// Scan decomposition: cluster of 8 CTAs per (head,batch) problem
#define CS   8
#define ESL  (DH/CS)      // 24 outputs per CTA per gate
#define NT   384          // 12 warps: 4 gates x 24 e x 4 d-quarters

// Scratch (device globals; no allocation allowed)
__device__ float g_xconv[BB*SS*DD];      // 25 MB
__device__ float g_pre[4*BB*SS*DD];      // 100 MB: gate pre-activations [g][b][s][d]
__device__ float g_y[BB*SS*DD];          // 25 MB: hidden states pre-LN

__device__ __forceinline__ uint32_t smem_u32(const void* p) {
    return (uint32_t)__cvta_generic_to_shared(p);
}
__device__ __forceinline__ void mbar_init(uint32_t addr, uint32_t count) {
    asm volatile("mbarrier.init.shared.b64 [%0], %1;" :: "r"(addr), "r"(count) : "memory");
}
// Arm: single arrival + expect tx bytes for the pending phase
__device__ __forceinline__ void mbar_arrive_expect_tx(uint32_t addr, uint32_t tx) {
    asm volatile("mbarrier.arrive.expect_tx.shared.b64 _, [%0], %1;"
                 :: "r"(addr), "r"(tx) : "memory");
}
// Bulk DSMEM copy: local smem -> peer CTA smem, completion on peer's mbarrier
__device__ __forceinline__ void bulk_to_peer(uint32_t dst_cluster, uint32_t src_cta,
                                             uint32_t bytes, uint32_t peer_mbar) {
    asm volatile(
        "cp.async.bulk.shared::cluster.shared::cta.mbarrier::complete_tx::bytes "
        "[%0], [%1], %2, [%3];"
        :: "r"(dst_cluster), "r"(src_cta), "r"(bytes), "r"(peer_mbar) : "memory");
}
// Parity wait, cluster-scope acquire (makes async-proxy writes visible)
__device__ __forceinline__ void mbar_wait_cluster(uint32_t addr, int parity) {
    asm volatile(
        "{\n\t"
        ".reg .pred P;\n\t"
        "WL_%=:\n\t"
        "mbarrier.try_wait.parity.acquire.cluster.shared::cta.b64 P, [%0], %1, 0x989680;\n\t"
        "@P bra.uni WD_%=;\n\t"
        "bra.uni WL_%=;\n\t"
        "WD_%=:\n\t"
        "}"
        :: "r"(addr), "r"(parity) : "memory");
}

// ---------------------------------------------------------------------------
// Stage 1: causal depthwise conv1d + bias + swish
// ---------------------------------------------------------------------------
__global__ void conv_swish_kernel(const float* __restrict__ x,
                                  const float* __restrict__ ck,
                                  const float* __restrict__ cb) {
    int idx = blockIdx.x * blockDim.x + threadIdx.x;
    if (idx >= BB*SS*DD) return;
    int d = idx % DD;
    int s = (idx / DD) % SS;
    float acc = cb[d];
#pragma unroll
    for (int j = 0; j < KK; j++) {
        int ss = s - (KK-1) + j;
        if (ss >= 0) acc = fmaf(x[idx + (j - (KK-1))*DD], ck[j*DD + d], acc);
    }
    g_xconv[idx] = acc / (1.f + expf(-acc));   // swish
}

// ---------------------------------------------------------------------------
// Stage 2: block-diagonal gate projections (64x64 smem-tiled fp32 GEMM)
// ---------------------------------------------------------------------------
__global__ __launch_bounds__(256)
void proj_gemm_kernel(const float* __restrict__ x,
                      const float* __restrict__ Wi, const float* __restrict__ Wf,
                      const float* __restrict__ Wz, const float* __restrict__ Wo) {
    int g = blockIdx.z >> 2;
    int h = blockIdx.z & 3;
    const float* src = (g < 2) ? g_xconv : x;
    const float* W = (g == 0) ? Wi : (g == 1) ? Wf : (g == 2) ? Wz : Wo;
    W += (size_t)h * DH * DH;

    int m0 = blockIdx.x * 64;
    int n0 = blockIdx.y * 64;
    int hcol = h * DH;

    __shared__ __align__(16) float As[16][64];
    __shared__ __align__(16) float Bs[16][64];

    int tid = threadIdx.x;
    int ty = tid >> 4, tx = tid & 15;
    float acc[4][4] = {};

    const float* Ab = src + (size_t)m0 * DD + hcol;

    for (int k0 = 0; k0 < DH; k0 += 16) {
        {   // A tile: 64 rows x 16 k (transposed store)
            int m  = tid >> 2;
            int kq = (tid & 3) * 4;
            float4 a4 = *(const float4*)(Ab + (size_t)m * DD + k0 + kq);
            As[kq+0][m] = a4.x; As[kq+1][m] = a4.y;
            As[kq+2][m] = a4.z; As[kq+3][m] = a4.w;
        }
        {   // B tile: 16 k x 64 e
            int k  = tid >> 4;
            int eq = (tid & 15) * 4;
            *(float4*)&Bs[k][eq] = *(const float4*)(W + (size_t)(k0+k)*DH + n0 + eq);
        }
        __syncthreads();
#pragma unroll
        for (int k = 0; k < 16; k++) {
            float4 a4 = *(const float4*)&As[k][ty*4];
            float4 b4 = *(const float4*)&Bs[k][tx*4];
            float a[4] = {a4.x, a4.y, a4.z, a4.w};
            float bv[4] = {b4.x, b4.y, b4.z, b4.w};
#pragma unroll
            for (int i = 0; i < 4; i++)
#pragma unroll
                for (int j = 0; j < 4; j++)
                    acc[i][j] = fmaf(a[i], bv[j], acc[i][j]);
        }
        __syncthreads();
    }

    float* C = g_pre + (size_t)g*MM*DD + (size_t)m0*DD + hcol + n0;
#pragma unroll
    for (int i = 0; i < 4; i++) {
        float4 v = { acc[i][0], acc[i][1], acc[i][2], acc[i][3] };
        *(float4*)(C + (size_t)(ty*4+i)*DD + tx*4) = v;
    }
}

// ---------------------------------------------------------------------------
// Stage 3: sequential sLSTM scan.
// 16 problems x cluster of 8 CTAs (128 CTAs), NT=384 (12 full warps).
// tid = g*96 + e*4 + dq : gate g, local output e (0..23), d-quarter dq.
// Each thread: 48 R coeffs in regs (d4-indices 4*qq+dq); 4-way combine via
// two shfl_xor. Gate nonlinearity in warp-0 lanes 0..23. h exchange: hv
// staged in smem (ping-pong), then ONE cp.async.bulk (96 B) per destination
// CTA, issued by lanes 0..7, completing on the destination's ping-pong
// mbarrier armed with expect_tx = DH*4 = 768 B (8 sources x 96 B).
// ---------------------------------------------------------------------------
__global__ void __cluster_dims__(CS, 1, 1) __launch_bounds__(NT, 1)
scan_kernel(const float* __restrict__ Rw, const float* __restrict__ cbias) {
    __shared__ __align__(16) float hbuf[2][DH];
    __shared__ __align__(16) float stage[2][ESL];
    __shared__ float pre_s[4*ESL];
    __shared__ __align__(8) unsigned long long mbar[2];

    int tid = threadIdx.x;
    int lane = tid & 31;
    uint32_t rank;
    asm("mov.u32 %0, %%cluster_ctarank;" : "=r"(rank));
    int prob = blockIdx.x / CS;        // 0..15
    int b = prob >> 2;
    int h = prob & 3;
    int g   = tid / 96;                // gate 0..3
    int r96 = tid % 96;
    int e   = r96 >> 2;                // 0..23
    int dq  = r96 & 3;                 // d-quarter
    int eg  = (int)rank * ESL + e;     // e within head, 0..191

    // R registers: qq covers d4-index (4*qq+dq): d = (4*qq+dq)*4 + j
    float Rreg[48];
    const float* Rcol = Rw + ((size_t)(g*NH + h) * DH) * DH + eg;
#pragma unroll
    for (int qq = 0; qq < 12; qq++) {
        int dbase = (4*qq + dq) * 4;
#pragma unroll
        for (int j = 0; j < 4; j++)
            Rreg[4*qq + j] = Rcol[(size_t)(dbase + j) * DH];
    }
    float bias = cbias[g*DD + h*DH + eg];
    const float* gp = g_pre + ((size_t)(g*BB + b) * SS) * DD + h*DH + eg;

    uint32_t hb0 = smem_u32(&hbuf[0][0]);
    uint32_t mb0 = smem_u32(&mbar[0]);
    uint32_t st0 = smem_u32(&stage[0][0]);

    // Lane-private peer addresses: warp-0 lane l (<8) talks to peer CTA l.
    uint32_t my_dst = 0, my_mb = 0;
    if (tid < CS) {
        asm("mapa.shared::cluster.u32 %0, %1, %2;" : "=r"(my_dst) : "r"(hb0), "r"(tid));
        asm("mapa.shared::cluster.u32 %0, %1, %2;" : "=r"(my_mb)  : "r"(mb0), "r"(tid));
    }
    uint32_t slice_off = (uint32_t)(rank * ESL * 4);   // my 96B slice within h

    for (int i = tid; i < 2*DH; i += NT) ((float*)hbuf)[i] = 0.f;
    if (tid == 0) {
        mbar_init(mb0,     1);
        mbar_init(mb0 + 8, 1);
        mbar_arrive_expect_tx(mb0,     DH*4);   // arm phase 0 of both
        mbar_arrive_expect_tx(mb0 + 8, DH*4);
    }
    asm volatile("barrier.cluster.arrive.aligned;" ::: "memory");
    asm volatile("barrier.cluster.wait.aligned;"   ::: "memory");

    // Cell state lives in warp-0 lanes 0..23 (lane == local e)
    float c = 0.f, n = 0.f, m = 0.f;
    int eg_w = (int)rank * ESL + lane;
    float* yout = g_y + ((size_t)b * SS) * DD + h*DH;

    float gin = (dq == 0) ? gp[0] : 0.f;
    int ph0 = 0, ph1 = 0;

    for (int s = 0; s < SS; s++) {
        int cur = s & 1;
        if (s) {
            if (cur) { mbar_wait_cluster(mb0 + 8, ph1); ph1 ^= 1;
                       if (tid == 0) mbar_arrive_expect_tx(mb0 + 8, DH*4); }
            else     { mbar_wait_cluster(mb0,     ph0); ph0 ^= 1;
                       if (tid == 0) mbar_arrive_expect_tx(mb0,     DH*4); }
        }
        // --- matvec: quarter-dot over 48 d values ---
        float a0 = 0.f, a1 = 0.f, a2 = 0.f, a3 = 0.f;
        const float4* h4p = (const float4*)hbuf[cur];
#pragma unroll
        for (int qq = 0; qq < 12; qq++) {
            float4 h4 = h4p[4*qq + dq];
            a0 = fmaf(Rreg[4*qq+0], h4.x, a0);
            a1 = fmaf(Rreg[4*qq+1], h4.y, a1);
            a2 = fmaf(Rreg[4*qq+2], h4.z, a2);
            a3 = fmaf(Rreg[4*qq+3], h4.w, a3);
        }
        float a = (a0 + a1) + (a2 + a3);
        a += __shfl_xor_sync(0xffffffffu, a, 1);   // combine d-quarters
        a += __shfl_xor_sync(0xffffffffu, a, 2);
        if (dq == 0) {
            pre_s[g*ESL + e] = a + gin + bias;
            if (s + 1 < SS) gin = gp[(size_t)(s+1) * DD];   // prefetch
        }
        __syncthreads();

        if (tid < 32) {
            float hv = 0.f;
            if (lane < ESL) {   // gate nonlinearity
                float it = pre_s[lane];
                float ft = pre_s[ESL   + lane];
                float zt = pre_s[2*ESL + lane];
                float ot = pre_s[3*ESL + lane];
                float mn = fmaxf(ft + m, it);
                float ia = __expf(it - mn);
                float fa = __expf(ft + m - mn);
                float t2 = __expf(-2.f * fabsf(zt));          // fast tanh
                float tz = copysignf((1.f - t2) / (1.f + t2), zt);
                c = fa*c + ia*tz;
                n = fa*n + ia;
                m = mn;
                float sig = 1.f / (1.f + __expf(-ot));
                hv = sig * c / n;
                yout[(size_t)s * DD + eg_w] = hv;
            }
            if (s + 1 < SS) {
                int nxt = cur ^ 1;
                if (lane < ESL) stage[nxt][lane] = hv;
                __syncwarp();
                asm volatile("fence.proxy.async.shared::cta;" ::: "memory");
                if (lane < CS)   // one 96B bulk per destination CTA
                    bulk_to_peer(my_dst + (uint32_t)(nxt*DH*4) + slice_off,
                                 st0 + (uint32_t)(nxt*ESL*4),
                                 ESL*4,
                                 my_mb + (uint32_t)(nxt*8));
            }
        }
        // pre_s reuse protected by next-step wait (phase needs our bulk,
        // issued after our pre_s reads). stage reuse protected by the
        // two-step dependency chain through peers (ping-pong buffer).
    }
    asm volatile("barrier.cluster.arrive.aligned;" ::: "memory");
    asm volatile("barrier.cluster.wait.aligned;"   ::: "memory");
}

// ---------------------------------------------------------------------------
// Stage 4: per-(b,s,head) layernorm over DH=192, scaled by gn_scale.
// ---------------------------------------------------------------------------
__global__ void ln_kernel(const float* __restrict__ gns, float* __restrict__ out) {
    int gidx = (blockIdx.x * blockDim.x + threadIdx.x) >> 5;
    int lane = threadIdx.x & 31;
    if (gidx >= BB*SS*NH) return;
    int h  = gidx & (NH-1);
    int bs = gidx >> 2;
    const float* yp = g_y + (size_t)bs * DD + h*DH;
    float v[6];
    float sum = 0.f;
#pragma unroll
    for (int i = 0; i < 6; i++) { v[i] = yp[lane + 32*i]; sum += v[i]; }
#pragma unroll
    for (int o = 16; o; o >>= 1) sum += __shfl_xor_sync(0xffffffffu, sum, o);
    float mu = sum * (1.f/DH);
    float sq = 0.f;
#pragma unroll
    for (int i = 0; i < 6; i++) { float t = v[i] - mu; sq += t*t; }
#pragma unroll
    for (int o = 16; o; o >>= 1) sq += __shfl_xor_sync(0xffffffffu, sq, o);
    float rs = rsqrtf(sq * (1.f/DH) + 1e-5f);
    float* op = out + (size_t)bs * DD + h*DH;
#pragma unroll
    for (int i = 0; i < 6; i++) {
        int e = lane + 32*i;
        op[e] = (v[i] - mu) * rs * gns[h*DH + e];
    }
}

// ---------------------------------------------------------------------------
extern "C" void kernel_launch(void* const* d_in, const int* in_sizes, int n_in,
                              void* d_out, int out_size) {
    const float* x     = (const float*)d_in[0];
    const float* ck    = (const float*)d_in[1];
    const float* cb    = (const float*)d_in[2];
    const float* Wi    = (const float*)d_in[3];
    const float* Wf    = (const float*)d_in[4];
    const float* Wz    = (const float*)d_in[5];
    const float* Wo    = (const float*)d_in[6];
    const float* R     = (const float*)d_in[7];
    const float* cbias = (const float*)d_in[8];
    const float* gns   = (const float*)d_in[9];
    float* out = (float*)d_out;

    conv_swish_kernel<<<(BB*SS*DD + 255)/256, 256>>>(x, ck, cb);

    dim3 gg(MM/64, DH/64, 16);   // (128, 3, 16)
    proj_gemm_kernel<<<gg, 256>>>(x, Wi, Wf, Wz, Wo);

    scan_kernel<<<BB*NH*CS, NT>>>(R, cbias);   // 128 CTAs, clusters of 8

    ln_kernel<<<(BB*SS*NH*32 + 255)/256, 256>>>(gns, out);
}

// round 15
// speedup vs baseline: 1.2827x; 1.2827x over previous
#include <cuda_runtime.h>
#include <cstdint>

// Problem constants
#define BB   4
#define SS   2048
#define DD   768
#define NH   4
#define KK   4
#define DH   192          // DD / NH
#define MM   (BB*SS)      // 8192 GEMM rows

// Scan decomposition: cluster of 4 CTAs per (head,batch) problem (r5 proven)
#define CS   4
#define SLC  (DH/CS)      // 48 outputs per CTA per gate
#define NT   384          // 4 gates x 24 e-pairs x 4 d-quarters

// Scratch (device globals; no allocation allowed)
__device__ float g_xconv[BB*SS*DD];      // 25 MB
__device__ float g_pre[4*BB*SS*DD];      // 100 MB: gate pre-activations [g][b][s][d]
__device__ float g_y[BB*SS*DD];          // 25 MB: hidden states pre-LN

__device__ __forceinline__ uint32_t smem_u32(const void* p) {
    return (uint32_t)__cvta_generic_to_shared(p);
}
// Packed fp32x2 FMA (Blackwell FFMA2; only reachable via PTX)
__device__ __forceinline__ void ffma2(unsigned long long& d,
                                      unsigned long long a, unsigned long long b) {
    asm("fma.rn.f32x2 %0, %1, %2, %0;" : "+l"(d) : "l"(a), "l"(b));
}
__device__ __forceinline__ unsigned long long pack2(float lo, float hi) {
    unsigned long long v;
    asm("mov.b64 %0, {%1, %2};" : "=l"(v) : "f"(lo), "f"(hi));
    return v;
}
__device__ __forceinline__ float2 unpack2(unsigned long long v) {
    float2 r;
    asm("mov.b64 {%0, %1}, %2;" : "=f"(r.x), "=f"(r.y) : "l"(v));
    return r;
}
// VOLATILE shared load: the compiler must not CSE/hoist these — the backing
// smem is mutated through channels it cannot see (tile refills after
// __syncthreads, remote st.shared::cluster). This was the r12 corruption bug.
__device__ __forceinline__ void lds_v2u64(uint32_t addr,
                                          unsigned long long& a, unsigned long long& b) {
    asm volatile("ld.shared.v2.b64 {%0, %1}, [%2];" : "=l"(a), "=l"(b) : "r"(addr));
}

// ---------------------------------------------------------------------------
// Stage 1: causal depthwise conv1d + bias + swish
// ---------------------------------------------------------------------------
__global__ void conv_swish_kernel(const float* __restrict__ x,
                                  const float* __restrict__ ck,
                                  const float* __restrict__ cb) {
    int idx = blockIdx.x * blockDim.x + threadIdx.x;
    if (idx >= BB*SS*DD) return;
    int d = idx % DD;
    int s = (idx / DD) % SS;
    float acc = cb[d];
#pragma unroll
    for (int j = 0; j < KK; j++) {
        int ss = s - (KK-1) + j;
        if (ss >= 0) acc = fmaf(x[idx + (j - (KK-1))*DD], ck[j*DD + d], acc);
    }
    g_xconv[idx] = acc / (1.f + expf(-acc));   // swish
}

// ---------------------------------------------------------------------------
// Stage 2: block-diagonal gate projections (64x64 tiled fp32 GEMM, FFMA2).
// A tile stored DUPLICATED in smem (As2[k][2i]=As2[k][2i+1]=a_i) so both
// FFMA2 operands come straight from ld.shared.v2.b64 (no splat movs).
// Inner loop per k: 3 LDS + 8 FFMA2 for 16 FMA.
// ---------------------------------------------------------------------------
__global__ __launch_bounds__(256)
void proj_gemm_kernel(const float* __restrict__ x,
                      const float* __restrict__ Wi, const float* __restrict__ Wf,
                      const float* __restrict__ Wz, const float* __restrict__ Wo) {
    int g = blockIdx.z >> 2;
    int h = blockIdx.z & 3;
    const float* src = (g < 2) ? g_xconv : x;
    const float* W = (g == 0) ? Wi : (g == 1) ? Wf : (g == 2) ? Wz : Wo;
    W += (size_t)h * DH * DH;

    int m0 = blockIdx.x * 64;
    int n0 = blockIdx.y * 64;
    int hcol = h * DH;

    __shared__ __align__(16) float As2[16][128];   // duplicated pairs
    __shared__ __align__(16) float Bs[16][64];

    int tid = threadIdx.x;
    int ty = tid >> 4, tx = tid & 15;
    unsigned long long acc2[4][2] = {};   // acc2[i][jp] = (C[i][2jp], C[i][2jp+1])

    const float* Ab = src + (size_t)m0 * DD + hcol;
    uint32_t as_base = smem_u32(&As2[0][0]);
    uint32_t bs_base = smem_u32(&Bs[0][0]);

    for (int k0 = 0; k0 < DH; k0 += 16) {
        {   // A tile: 64 rows x 16 k, duplicated store
            int m  = tid >> 2;
            int kq = (tid & 3) * 4;
            float4 a4 = *(const float4*)(Ab + (size_t)m * DD + k0 + kq);
            As2[kq+0][2*m] = a4.x; As2[kq+0][2*m+1] = a4.x;
            As2[kq+1][2*m] = a4.y; As2[kq+1][2*m+1] = a4.y;
            As2[kq+2][2*m] = a4.z; As2[kq+2][2*m+1] = a4.z;
            As2[kq+3][2*m] = a4.w; As2[kq+3][2*m+1] = a4.w;
        }
        {   // B tile: 16 k x 64 e
            int k  = tid >> 4;
            int eq = (tid & 15) * 4;
            *(float4*)&Bs[k][eq] = *(const float4*)(W + (size_t)(k0+k)*DH + n0 + eq);
        }
        __syncthreads();
#pragma unroll
        for (int k = 0; k < 16; k++) {
            unsigned long long aa0, aa1, aa2, aa3, bb0, bb1;
            uint32_t aaddr = as_base + (uint32_t)(k*512 + ty*32);
            lds_v2u64(aaddr,      aa0, aa1);   // (a0,a0),(a1,a1)
            lds_v2u64(aaddr + 16, aa2, aa3);   // (a2,a2),(a3,a3)
            lds_v2u64(bs_base + (uint32_t)(k*256 + tx*16), bb0, bb1); // (b0,b1),(b2,b3)
            ffma2(acc2[0][0], aa0, bb0); ffma2(acc2[0][1], aa0, bb1);
            ffma2(acc2[1][0], aa1, bb0); ffma2(acc2[1][1], aa1, bb1);
            ffma2(acc2[2][0], aa2, bb0); ffma2(acc2[2][1], aa2, bb1);
            ffma2(acc2[3][0], aa3, bb0); ffma2(acc2[3][1], aa3, bb1);
        }
        __syncthreads();
    }

    float* C = g_pre + (size_t)g*MM*DD + (size_t)m0*DD + hcol + n0;
#pragma unroll
    for (int i = 0; i < 4; i++) {
        float2 c01 = unpack2(acc2[i][0]);
        float2 c23 = unpack2(acc2[i][1]);
        float4 v = { c01.x, c01.y, c23.x, c23.y };
        *(float4*)(C + (size_t)(ty*4+i)*DD + tx*4) = v;
    }
}

// ---------------------------------------------------------------------------
// Stage 3: sequential sLSTM scan (r5 sync mechanism, FFMA2 matvec).
// 16 problems x cluster of 4 CTAs (64 CTAs), NT=384 (12 warps).
// tid = g*96 + ep*4 + dq : gate g, e-pair ep (outputs ep and ep+24 of this
// CTA's 48-slice), d-quarter dq (48 d values = 24 f32x2 pairs).
// Each thread: 48 packed R coeffs (2 outputs x 24 pairs) in registers; h read
// as ld.shared.v2.b64 (12 loads), 48 FFMA2; 4-way combine via 2 shfl_xor.
// Gate nonlinearity in threads 0..47; h broadcast via st.shared::cluster x4;
// step sync via barrier.cluster (the only mechanism measured fast).
// ---------------------------------------------------------------------------
__global__ void __cluster_dims__(CS, 1, 1) __launch_bounds__(NT, 1)
scan_kernel(const float* __restrict__ Rw, const float* __restrict__ cbias) {
    __shared__ __align__(16) float hbuf[2][DH];
    __shared__ float pre_s[4*SLC];

    int tid = threadIdx.x;
    uint32_t rank;
    asm("mov.u32 %0, %%cluster_ctarank;" : "=r"(rank));
    int prob = blockIdx.x / CS;        // 0..15
    int b = prob >> 2;
    int h = prob & 3;
    int g  = tid / 96;                 // gate 0..3
    int r  = tid % 96;
    int ep = r >> 2;                   // 0..23 (outputs ep, ep+24)
    int dq = r & 3;                    // d-quarter (48 d each)
    int eg0 = (int)rank * SLC + ep;    // global e of output 0
    int eg1 = eg0 + 24;

    // Packed R registers: pair p covers d = dq*48 + 2p, 2p+1
    unsigned long long Rp0[24], Rp1[24];
    const float* Rb = Rw + ((size_t)(g*NH + h) * DH) * DH;
#pragma unroll
    for (int p = 0; p < 24; p++) {
        int d0 = dq*48 + 2*p;
        Rp0[p] = pack2(Rb[(size_t)d0*DH + eg0], Rb[(size_t)(d0+1)*DH + eg0]);
        Rp1[p] = pack2(Rb[(size_t)d0*DH + eg1], Rb[(size_t)(d0+1)*DH + eg1]);
    }
    float bias0 = cbias[g*DD + h*DH + eg0];
    float bias1 = cbias[g*DD + h*DH + eg1];
    const float* gpb = g_pre + ((size_t)(g*BB + b) * SS) * DD + h*DH;
    float gin0 = 0.f, gin1 = 0.f;
    if (dq == 0) { gin0 = gpb[eg0]; gin1 = gpb[eg1]; }

    // Peer smem addresses for h broadcast
    uint32_t hb0 = smem_u32(&hbuf[0][0]);
    uint32_t peer_hb[CS];
#pragma unroll
    for (int p = 0; p < CS; p++)
        asm("mapa.shared::cluster.u32 %0, %1, %2;"
            : "=r"(peer_hb[p]) : "r"(hb0), "r"(p));

    for (int i = tid; i < 2*DH; i += NT) ((float*)hbuf)[i] = 0.f;
    asm volatile("barrier.cluster.arrive.aligned;" ::: "memory");
    asm volatile("barrier.cluster.wait.aligned;"   ::: "memory");

    // Cell state in threads 0..47 (thread tid owns local e = tid)
    float c = 0.f, n = 0.f, m = 0.f;
    int eg_w = (int)rank * SLC + tid;  // only meaningful for tid < 48
    float* yout = g_y + ((size_t)b * SS) * DD + h*DH;

    for (int s = 0; s < SS; s++) {
        int cur = s & 1;
        // --- matvec: 2 outputs x 48 d via FFMA2 (4 indep chains) ---
        unsigned long long acc0a = 0ull, acc0b = 0ull, acc1a = 0ull, acc1b = 0ull;
        uint32_t haddr = hb0 + (uint32_t)((cur*DH + dq*48) * 4);
#pragma unroll
        for (int i = 0; i < 12; i++) {
            unsigned long long h0, h1;
            lds_v2u64(haddr + (uint32_t)(i*16), h0, h1);
            ffma2(acc0a, Rp0[2*i],   h0);
            ffma2(acc0b, Rp0[2*i+1], h1);
            ffma2(acc1a, Rp1[2*i],   h0);
            ffma2(acc1b, Rp1[2*i+1], h1);
        }
        float2 u0a = unpack2(acc0a), u0b = unpack2(acc0b);
        float2 u1a = unpack2(acc1a), u1b = unpack2(acc1b);
        float a0 = (u0a.x + u0a.y) + (u0b.x + u0b.y);
        float a1 = (u1a.x + u1a.y) + (u1b.x + u1b.y);
        a0 += __shfl_xor_sync(0xffffffffu, a0, 1);
        a1 += __shfl_xor_sync(0xffffffffu, a1, 1);
        a0 += __shfl_xor_sync(0xffffffffu, a0, 2);
        a1 += __shfl_xor_sync(0xffffffffu, a1, 2);
        if (dq == 0) {
            pre_s[g*SLC + ep]      = a0 + gin0 + bias0;
            pre_s[g*SLC + ep + 24] = a1 + gin1 + bias1;
            if (s + 1 < SS) {   // prefetch next step's gate inputs
                gin0 = gpb[(size_t)(s+1) * DD + eg0];
                gin1 = gpb[(size_t)(s+1) * DD + eg1];
            }
        }
        __syncthreads();

        if (tid < SLC) {   // gate nonlinearity + broadcast
            float it = pre_s[tid];
            float ft = pre_s[SLC   + tid];
            float zt = pre_s[2*SLC + tid];
            float ot = pre_s[3*SLC + tid];
            float mn = fmaxf(ft + m, it);
            float ia = __expf(it - mn);
            float fa = __expf(ft + m - mn);
            float t2 = __expf(-2.f * fabsf(zt));          // fast tanh, safe
            float tz = copysignf((1.f - t2) / (1.f + t2), zt);
            c = fa*c + ia*tz;
            n = fa*n + ia;
            m = mn;
            float sig = 1.f / (1.f + __expf(-ot));
            float hv = sig * c / n;
            yout[(size_t)s * DD + eg_w] = hv;
            if (s + 1 < SS) {
                uint32_t off = (uint32_t)((((cur ^ 1) * DH) + eg_w) * 4);
#pragma unroll
                for (int p = 0; p < CS; p++)
                    asm volatile("st.shared::cluster.f32 [%0], %1;"
                                 :: "r"(peer_hb[p] + off), "f"(hv) : "memory");
            }
        }
        asm volatile("barrier.cluster.arrive.aligned;" ::: "memory");
        asm volatile("barrier.cluster.wait.aligned;"   ::: "memory");
    }
    asm volatile("barrier.cluster.arrive.aligned;" ::: "memory");
    asm volatile("barrier.cluster.wait.aligned;"   ::: "memory");
}

// ---------------------------------------------------------------------------
// Stage 4: per-(b,s,head) layernorm over DH=192, scaled by gn_scale.
// ---------------------------------------------------------------------------
__global__ void ln_kernel(const float* __restrict__ gns, float* __restrict__ out) {
    int gidx = (blockIdx.x * blockDim.x + threadIdx.x) >> 5;
    int lane = threadIdx.x & 31;
    if (gidx >= BB*SS*NH) return;
    int h  = gidx & (NH-1);
    int bs = gidx >> 2;
    const float* yp = g_y + (size_t)bs * DD + h*DH;
    float v[6];
    float sum = 0.f;
#pragma unroll
    for (int i = 0; i < 6; i++) { v[i] = yp[lane + 32*i]; sum += v[i]; }
#pragma unroll
    for (int o = 16; o; o >>= 1) sum += __shfl_xor_sync(0xffffffffu, sum, o);
    float mu = sum * (1.f/DH);
    float sq = 0.f;
#pragma unroll
    for (int i = 0; i < 6; i++) { float t = v[i] - mu; sq += t*t; }
#pragma unroll
    for (int o = 16; o; o >>= 1) sq += __shfl_xor_sync(0xffffffffu, sq, o);
    float rs = rsqrtf(sq * (1.f/DH) + 1e-5f);
    float* op = out + (size_t)bs * DD + h*DH;
#pragma unroll
    for (int i = 0; i < 6; i++) {
        int e = lane + 32*i;
        op[e] = (v[i] - mu) * rs * gns[h*DH + e];
    }
}

// ---------------------------------------------------------------------------
extern "C" void kernel_launch(void* const* d_in, const int* in_sizes, int n_in,
                              void* d_out, int out_size) {
    const float* x     = (const float*)d_in[0];
    const float* ck    = (const float*)d_in[1];
    const float* cb    = (const float*)d_in[2];
    const float* Wi    = (const float*)d_in[3];
    const float* Wf    = (const float*)d_in[4];
    const float* Wz    = (const float*)d_in[5];
    const float* Wo    = (const float*)d_in[6];
    const float* R     = (const float*)d_in[7];
    const float* cbias = (const float*)d_in[8];
    const float* gns   = (const float*)d_in[9];
    float* out = (float*)d_out;

    conv_swish_kernel<<<(BB*SS*DD + 255)/256, 256>>>(x, ck, cb);

    dim3 gg(MM/64, DH/64, 16);   // (128, 3, 16)
    proj_gemm_kernel<<<gg, 256>>>(x, Wi, Wf, Wz, Wo);

    scan_kernel<<<BB*NH*CS, NT>>>(R, cbias);   // 64 CTAs, clusters of 4

    ln_kernel<<<(BB*SS*NH*32 + 255)/256, 256>>>(gns, out);
}

// round 17
// speedup vs baseline: 1.5669x; 1.2215x over previous
#include <cuda_runtime.h>
#include <cstdint>

// Problem constants
#define BB   4
#define SS   2048
#define DD   768
#define NH   4
#define KK   4
#define DH   192          // DD / NH
#define MM   (BB*SS)      // 8192 GEMM rows

// Scan decomposition: cluster of 4 CTAs per (head,batch) problem (r5 proven)
#define CS   4
#define SLC  (DH/CS)      // 48 outputs per CTA per gate
#define NT   384          // 4 gates x 48 e x 2 d-halves -> 12 warps, 3/SMSP balanced

// Scratch (device globals; no allocation allowed)
__device__ float g_xconv[BB*SS*DD];      // 25 MB
__device__ float g_pre[4*BB*SS*DD];      // 100 MB: gate pre-activations [g][b][s][d]
__device__ float g_y[BB*SS*DD];          // 25 MB: hidden states pre-LN

__device__ __forceinline__ uint32_t smem_u32(const void* p) {
    return (uint32_t)__cvta_generic_to_shared(p);
}

// ---------------------------------------------------------------------------
// Stage 1: causal depthwise conv1d + bias + swish
// ---------------------------------------------------------------------------
__global__ void conv_swish_kernel(const float* __restrict__ x,
                                  const float* __restrict__ ck,
                                  const float* __restrict__ cb) {
    int idx = blockIdx.x * blockDim.x + threadIdx.x;
    if (idx >= BB*SS*DD) return;
    int d = idx % DD;
    int s = (idx / DD) % SS;
    float acc = cb[d];
#pragma unroll
    for (int j = 0; j < KK; j++) {
        int ss = s - (KK-1) + j;
        if (ss >= 0) acc = fmaf(x[idx + (j - (KK-1))*DD], ck[j*DD + d], acc);
    }
    g_xconv[idx] = acc / (1.f + expf(-acc));   // swish
}

// ---------------------------------------------------------------------------
// Stage 2: block-diagonal gate projections (64x64 smem-tiled fp32 GEMM).
// r8-proven version: plain C++ float4 smem loads, scalar FFMA.
// ---------------------------------------------------------------------------
__global__ __launch_bounds__(256)
void proj_gemm_kernel(const float* __restrict__ x,
                      const float* __restrict__ Wi, const float* __restrict__ Wf,
                      const float* __restrict__ Wz, const float* __restrict__ Wo) {
    int g = blockIdx.z >> 2;
    int h = blockIdx.z & 3;
    const float* src = (g < 2) ? g_xconv : x;
    const float* W = (g == 0) ? Wi : (g == 1) ? Wf : (g == 2) ? Wz : Wo;
    W += (size_t)h * DH * DH;

    int m0 = blockIdx.x * 64;
    int n0 = blockIdx.y * 64;
    int hcol = h * DH;

    __shared__ __align__(16) float As[16][64];
    __shared__ __align__(16) float Bs[16][64];

    int tid = threadIdx.x;
    int ty = tid >> 4, tx = tid & 15;
    float acc[4][4] = {};

    const float* Ab = src + (size_t)m0 * DD + hcol;

    for (int k0 = 0; k0 < DH; k0 += 16) {
        {   // A tile: 64 rows x 16 k (transposed store)
            int m  = tid >> 2;
            int kq = (tid & 3) * 4;
            float4 a4 = *(const float4*)(Ab + (size_t)m * DD + k0 + kq);
            As[kq+0][m] = a4.x; As[kq+1][m] = a4.y;
            As[kq+2][m] = a4.z; As[kq+3][m] = a4.w;
        }
        {   // B tile: 16 k x 64 e
            int k  = tid >> 4;
            int eq = (tid & 15) * 4;
            *(float4*)&Bs[k][eq] = *(const float4*)(W + (size_t)(k0+k)*DH + n0 + eq);
        }
        __syncthreads();
#pragma unroll
        for (int k = 0; k < 16; k++) {
            float4 a4 = *(const float4*)&As[k][ty*4];
            float4 b4 = *(const float4*)&Bs[k][tx*4];
            float a[4] = {a4.x, a4.y, a4.z, a4.w};
            float bv[4] = {b4.x, b4.y, b4.z, b4.w};
#pragma unroll
            for (int i = 0; i < 4; i++)
#pragma unroll
                for (int j = 0; j < 4; j++)
                    acc[i][j] = fmaf(a[i], bv[j], acc[i][j]);
        }
        __syncthreads();
    }

    float* C = g_pre + (size_t)g*MM*DD + (size_t)m0*DD + hcol + n0;
#pragma unroll
    for (int i = 0; i < 4; i++) {
        float4 v = { acc[i][0], acc[i][1], acc[i][2], acc[i][3] };
        *(float4*)(C + (size_t)(ty*4+i)*DD + tx*4) = v;
    }
}

// ---------------------------------------------------------------------------
// Stage 3: sequential sLSTM scan.
// 16 problems x cluster of 4 CTAs (64 CTAs), NT=384 (12 warps, 3/SMSP even).
// tid = g*96 + e*2 + dh : gate g, local output e (0..47), d-half dh.
// Each thread: 96 R coeffs in registers (d4-indices 2q+dh, interleaved so the
// warp's dual-address LDS.128 stays conflict-free); halves combine via one
// shfl_xor(1). Gate nonlinearity + broadcast in threads 0..47 (fast __expf /
// tanh). h exchange: st.shared::cluster x4 + barrier.cluster (the only
// mechanism measured fast across r5..r10).
// ---------------------------------------------------------------------------
__global__ void __cluster_dims__(CS, 1, 1) __launch_bounds__(NT, 1)
scan_kernel(const float* __restrict__ Rw, const float* __restrict__ cbias) {
    __shared__ __align__(16) float hbuf[2][DH];
    __shared__ float pre_s[4*SLC];

    int tid = threadIdx.x;
    uint32_t rank;
    asm("mov.u32 %0, %%cluster_ctarank;" : "=r"(rank));
    int prob = blockIdx.x / CS;        // 0..15
    int b = prob >> 2;
    int h = prob & 3;
    int g  = tid / 96;                 // gate 0..3
    int r  = tid % 96;
    int e  = r >> 1;                   // 0..47
    int dh = r & 1;                    // d-half
    int eg = (int)rank * SLC + e;      // e within head, 0..191

    // R registers: group q covers d4-index (2q+dh), i.e. d = (2q+dh)*4 + j
    float Rreg[96];
    const float* Rcol = Rw + ((size_t)(g*NH + h) * DH) * DH + eg;
#pragma unroll
    for (int q = 0; q < 24; q++) {
        int dbase = (2*q + dh) * 4;
#pragma unroll
        for (int j = 0; j < 4; j++)
            Rreg[4*q + j] = Rcol[(size_t)(dbase + j) * DH];
    }
    float bias = cbias[g*DD + h*DH + eg];
    const float* gp = g_pre + ((size_t)(g*BB + b) * SS) * DD + h*DH + eg;
    float gin = (dh == 0) ? gp[0] : 0.f;

    // Peer smem addresses for h broadcast
    uint32_t hb0 = smem_u32(&hbuf[0][0]);
    uint32_t peer_hb[CS];
#pragma unroll
    for (int p = 0; p < CS; p++)
        asm("mapa.shared::cluster.u32 %0, %1, %2;"
            : "=r"(peer_hb[p]) : "r"(hb0), "r"(p));

    for (int i = tid; i < 2*DH; i += NT) ((float*)hbuf)[i] = 0.f;
    asm volatile("barrier.cluster.arrive.aligned;" ::: "memory");
    asm volatile("barrier.cluster.wait.aligned;"   ::: "memory");

    // Cell state in threads 0..47 (thread tid owns local e = tid)
    float c = 0.f, n = 0.f, m = 0.f;
    int eg_w = (int)rank * SLC + tid;  // only meaningful for tid < 48
    float* yout = g_y + ((size_t)b * SS) * DD + h*DH;

    for (int s = 0; s < SS; s++) {
        int cur = s & 1;
        // --- matvec: half-dot over 96 d values, 4 indep FMA chains ---
        float a0 = 0.f, a1 = 0.f, a2 = 0.f, a3 = 0.f;
        const float4* h4p = (const float4*)hbuf[cur];
#pragma unroll
        for (int q = 0; q < 24; q++) {
            float4 h4 = h4p[2*q + dh];
            a0 = fmaf(Rreg[4*q+0], h4.x, a0);
            a1 = fmaf(Rreg[4*q+1], h4.y, a1);
            a2 = fmaf(Rreg[4*q+2], h4.z, a2);
            a3 = fmaf(Rreg[4*q+3], h4.w, a3);
        }
        float a = (a0 + a1) + (a2 + a3);
        a += __shfl_xor_sync(0xffffffffu, a, 1);   // combine d-halves
        if (dh == 0) {
            pre_s[g*SLC + e] = a + gin + bias;
            if (s + 1 < SS) gin = gp[(size_t)(s+1) * DD];   // prefetch
        }
        __syncthreads();

        if (tid < SLC) {   // gate nonlinearity + broadcast (e = tid)
            float it = pre_s[tid];
            float ft = pre_s[SLC   + tid];
            float zt = pre_s[2*SLC + tid];
            float ot = pre_s[3*SLC + tid];
            float mn = fmaxf(ft + m, it);
            float ia = __expf(it - mn);
            float fa = __expf(ft + m - mn);
            float t2 = __expf(-2.f * fabsf(zt));          // fast tanh, safe
            float tz = copysignf((1.f - t2) / (1.f + t2), zt);
            c = fa*c + ia*tz;
            n = fa*n + ia;
            m = mn;
            float sig = 1.f / (1.f + __expf(-ot));
            float hv = sig * c / n;
            if (s + 1 < SS) {   // broadcast first (critical path), y after
                uint32_t off = (uint32_t)((((cur ^ 1) * DH) + eg_w) * 4);
#pragma unroll
                for (int p = 0; p < CS; p++)
                    asm volatile("st.shared::cluster.f32 [%0], %1;"
                                 :: "r"(peer_hb[p] + off), "f"(hv) : "memory");
            }
            yout[(size_t)s * DD + eg_w] = hv;
        }
        asm volatile("barrier.cluster.arrive.aligned;" ::: "memory");
        asm volatile("barrier.cluster.wait.aligned;"   ::: "memory");
    }
    asm volatile("barrier.cluster.arrive.aligned;" ::: "memory");
    asm volatile("barrier.cluster.wait.aligned;"   ::: "memory");
}

// ---------------------------------------------------------------------------
// Stage 4: per-(b,s,head) layernorm over DH=192, scaled by gn_scale.
// ---------------------------------------------------------------------------
__global__ void ln_kernel(const float* __restrict__ gns, float* __restrict__ out) {
    int gidx = (blockIdx.x * blockDim.x + threadIdx.x) >> 5;
    int lane = threadIdx.x & 31;
    if (gidx >= BB*SS*NH) return;
    int h  = gidx & (NH-1);
    int bs = gidx >> 2;
    const float* yp = g_y + (size_t)bs * DD + h*DH;
    float v[6];
    float sum = 0.f;
#pragma unroll
    for (int i = 0; i < 6; i++) { v[i] = yp[lane + 32*i]; sum += v[i]; }
#pragma unroll
    for (int o = 16; o; o >>= 1) sum += __shfl_xor_sync(0xffffffffu, sum, o);
    float mu = sum * (1.f/DH);
    float sq = 0.f;
#pragma unroll
    for (int i = 0; i < 6; i++) { float t = v[i] - mu; sq += t*t; }
#pragma unroll
    for (int o = 16; o; o >>= 1) sq += __shfl_xor_sync(0xffffffffu, sq, o);
    float rs = rsqrtf(sq * (1.f/DH) + 1e-5f);
    float* op = out + (size_t)bs * DD + h*DH;
#pragma unroll
    for (int i = 0; i < 6; i++) {
        int e = lane + 32*i;
        op[e] = (v[i] - mu) * rs * gns[h*DH + e];
    }
}

// ---------------------------------------------------------------------------
extern "C" void kernel_launch(void* const* d_in, const int* in_sizes, int n_in,
                              void* d_out, int out_size) {
    const float* x     = (const float*)d_in[0];
    const float* ck    = (const float*)d_in[1];
    const float* cb    = (const float*)d_in[2];
    const float* Wi    = (const float*)d_in[3];
    const float* Wf    = (const float*)d_in[4];
    const float* Wz    = (const float*)d_in[5];
    const float* Wo    = (const float*)d_in[6];
    const float* R     = (const float*)d_in[7];
    const float* cbias = (const float*)d_in[8];
    const float* gns   = (const float*)d_in[9];
    float* out = (float*)d_out;

    conv_swish_kernel<<<(BB*SS*DD + 255)/256, 256>>>(x, ck, cb);

    dim3 gg(MM/64, DH/64, 16);   // (128, 3, 16)
    proj_gemm_kernel<<<gg, 256>>>(x, Wi, Wf, Wz, Wo);

    scan_kernel<<<BB*NH*CS, NT>>>(R, cbias);   // 64 CTAs, clusters of 4

    ln_kernel<<<(BB*SS*NH*32 + 255)/256, 256>>>(gns, out);
}